// round 15
// baseline (speedup 1.0000x reference)
#include <cuda_runtime.h>
#include <cuda_bf16.h>
#include <cstdint>

// ---------------------------------------------------------------------------
// Binarized MLP. Weights exactly +-1; activations in 16-bit fixed point
// v = s*(256*hi + lo) -> GEMM exact in int32 via two K-phases (acc <<= 8).
// Layer 1: hi s8 / lo s8, mma s8*s8.  Layers 2/3 (v>=0): hi u8 / lo u8,
// mma u8*s8.
// R15: GEMM experiment driven by first real GEMM ncu (tensor=65.5% idle 35%):
// CTA 128x256, 8 warps (64x64), 1 CTA/SM, 3-stage. Halves barriers/SM-ktile
// and cuts cp.async bytes 25% vs the 360us config. All else frozen.
// ---------------------------------------------------------------------------

#define BATCH 16384
#define GEMM_SMEM (3 * 49152)

__device__ __align__(256) int8_t g_act[(size_t)BATCH * 2048];    // hi | lo
__device__ __align__(256) int8_t g_wcat[3][(size_t)1024 * 2048]; // sign w per layer
__device__ __align__(256) float  g_h[(size_t)BATCH * 1024];
__device__ float g_sum[3][1024];
__device__ float g_sumsq[3][1024];

// ---------------------------------------------------------------------------
// PTX helpers (baseline PTX; compute_100 target has no tcgen05)
// ---------------------------------------------------------------------------
__device__ __forceinline__ uint32_t smem_u32(const void* p) {
    uint32_t a;
    asm("{ .reg .u64 t; cvta.to.shared.u64 t, %1; cvt.u32.u64 %0, t; }"
        : "=r"(a) : "l"(p));
    return a;
}
__device__ __forceinline__ void cp16(uint32_t dst, const void* src) {
    asm volatile("cp.async.cg.shared.global [%0], [%1], 16;"
                 :: "r"(dst), "l"(src) : "memory");
}
__device__ __forceinline__ void cp_commit() {
    asm volatile("cp.async.commit_group;" ::: "memory");
}
__device__ __forceinline__ void ldmx4(uint32_t* r, uint32_t addr) {
    asm volatile("ldmatrix.sync.aligned.m8n8.x4.shared.b16 {%0,%1,%2,%3}, [%4];"
                 : "=r"(r[0]), "=r"(r[1]), "=r"(r[2]), "=r"(r[3]) : "r"(addr));
}
__device__ __forceinline__ void mma_s8(int* c, const uint32_t* a, const uint32_t* b) {
    asm volatile(
        "mma.sync.aligned.m16n8k32.row.col.s32.s8.s8.s32 "
        "{%0,%1,%2,%3}, {%4,%5,%6,%7}, {%8,%9}, {%0,%1,%2,%3};"
        : "+r"(c[0]), "+r"(c[1]), "+r"(c[2]), "+r"(c[3])
        : "r"(a[0]), "r"(a[1]), "r"(a[2]), "r"(a[3]), "r"(b[0]), "r"(b[1]));
}
__device__ __forceinline__ void mma_u8(int* c, const uint32_t* a, const uint32_t* b) {
    asm volatile(
        "mma.sync.aligned.m16n8k32.row.col.s32.u8.s8.s32 "
        "{%0,%1,%2,%3}, {%4,%5,%6,%7}, {%8,%9}, {%0,%1,%2,%3};"
        : "+r"(c[0]), "+r"(c[1]), "+r"(c[2]), "+r"(c[3])
        : "r"(a[0]), "r"(a[1]), "r"(a[2]), "r"(a[3]), "r"(b[0]), "r"(b[1]));
}

// ---------------------------------------------------------------------------
// Merged prep: y == 0 -> prep_x (4 rows per block, MLP=4);
//              y in 1..3 -> binarize layer y-1 (blocks x < 256 active).
// ---------------------------------------------------------------------------
__global__ __launch_bounds__(256) void prep_all_kernel(
    const float* __restrict__ x, const float* __restrict__ w1,
    const float* __restrict__ w2, const float* __restrict__ w3) {
    int t = threadIdx.x;

    if (blockIdx.y == 0) {
        int r0 = blockIdx.x * 4;
        if (t < 196) {
            float4 xv[4];
#pragma unroll
            for (int i = 0; i < 4; i++)
                xv[i] = reinterpret_cast<const float4*>(x + (size_t)(r0 + i) * 784)[t];
#pragma unroll
            for (int i = 0; i < 4; i++) {
                float f[4] = {xv[i].x, xv[i].y, xv[i].z, xv[i].w};
                uint8_t hv[4], lv[4];
#pragma unroll
                for (int j = 0; j < 4; j++) {
                    int hi = __float2int_rn(f[j] * 16.0f);
                    hi = max(-127, min(127, hi));
                    int lo = __float2int_rn(f[j] * 4096.0f - 256.0f * hi);
                    lo = max(-128, min(127, lo));
                    hv[j] = (uint8_t)(int8_t)hi;
                    lv[j] = (uint8_t)(int8_t)lo;
                }
                int8_t* dst = g_act + (size_t)(r0 + i) * 1792;
                *reinterpret_cast<uchar4*>(dst + t * 4) =
                    make_uchar4(hv[0], hv[1], hv[2], hv[3]);
                *reinterpret_cast<uchar4*>(dst + 896 + t * 4) =
                    make_uchar4(lv[0], lv[1], lv[2], lv[3]);
            }
        } else if (t < 224) {
            int off = 784 + (t - 196) * 4;
#pragma unroll
            for (int i = 0; i < 4; i++) {
                int8_t* dst = g_act + (size_t)(r0 + i) * 1792;
                *reinterpret_cast<uchar4*>(dst + off) = make_uchar4(0, 0, 0, 0);
                *reinterpret_cast<uchar4*>(dst + 896 + off) = make_uchar4(0, 0, 0, 0);
            }
        }
        return;
    }

    int layer = blockIdx.y - 1;
    if (blockIdx.x >= 256) return;
    const float* w = (layer == 0) ? w1 : ((layer == 1) ? w2 : w3);
    int K = (layer == 0) ? 784 : 1024;
    int half = (layer == 0) ? 896 : 1024;
    int stride = half * 2;

    if (blockIdx.x == 0) {
        for (int j = t; j < 1024; j += 256) {
            g_sum[layer][j] = 0.0f;
            g_sumsq[layer][j] = 0.0f;
        }
    }

    int per_row = half >> 4;
    int idx = blockIdx.x * 256 + t;
    int n = idx / per_row;
    if (n >= 1024) return;
    int k16 = (idx - n * per_row) << 4;

    uint32_t pk[4] = {0, 0, 0, 0};
    if (k16 < K) {
        const float4* wp = reinterpret_cast<const float4*>(w + (size_t)n * K + k16);
#pragma unroll
        for (int q = 0; q < 4; q++) {
            float4 wv = wp[q];
            uint32_t b0 = (wv.x >= 0.0f) ? 0x01u : 0xFFu;
            uint32_t b1 = (wv.y >= 0.0f) ? 0x01u : 0xFFu;
            uint32_t b2 = (wv.z >= 0.0f) ? 0x01u : 0xFFu;
            uint32_t b3 = (wv.w >= 0.0f) ? 0x01u : 0xFFu;
            pk[q] = b0 | (b1 << 8) | (b2 << 16) | (b3 << 24);
        }
    }
    int4 v = make_int4((int)pk[0], (int)pk[1], (int)pk[2], (int)pk[3]);
    int8_t* base = g_wcat[layer] + (size_t)n * stride + k16;
    *reinterpret_cast<int4*>(base) = v;
    *reinterpret_cast<int4*>(base + half) = v;
}

// ---------------------------------------------------------------------------
// int8 GEMM: g_h = scale*(256*(hi@W) + lo@W), fused column stats.
// R15: CTA 128x256, 8 warps (2x4, warp 64x64), k-tile 128B, 3-stage cp.async,
// 1 CTA/SM (144KB smem). grid = (N=4, M=128).
// ---------------------------------------------------------------------------
template <int LDA, int KT, int UNS>
__global__ __launch_bounds__(256, 1) void gemm_s8_kernel(float scale, int layer) {
    constexpr int HIT = KT / 2;
    extern __shared__ char smem[];
    uint32_t sb = smem_u32(smem);
    int tid = threadIdx.x, lane = tid & 31, warp = tid >> 5;
    int wm = (warp & 1) * 64;
    int wn = (warp >> 1) * 64;                   // 0..192
    int n0 = blockIdx.x * 256, m0 = blockIdx.y * 128;
    const int8_t* A = g_act;
    const int8_t* W = g_wcat[layer];

    auto load_stage = [&](int s, int kt) {
        uint32_t baseA = sb + (uint32_t)s * 49152u;
        uint32_t baseB = baseA + 16384u;
        const int8_t* Ap = A + (size_t)m0 * LDA + kt * 128;
        const int8_t* Wp = W + (size_t)n0 * LDA + kt * 128;
#pragma unroll
        for (int i = 0; i < 4; i++) {            // A: 1024 16B chunks
            int idx = tid + i * 256;
            int row = idx >> 3, ck = idx & 7;
            uint32_t sw = (uint32_t)(row * 128 + ((ck ^ (row & 7)) << 4));
            cp16(baseA + sw, Ap + (size_t)row * LDA + ck * 16);
        }
#pragma unroll
        for (int i = 0; i < 8; i++) {            // B: 2048 16B chunks (256 rows)
            int idx = tid + i * 256;
            int row = idx >> 3, ck = idx & 7;
            uint32_t sw = (uint32_t)(row * 128 + ((ck ^ (row & 7)) << 4));
            cp16(baseB + sw, Wp + (size_t)row * LDA + ck * 16);
        }
        cp_commit();
    };

    load_stage(0, 0);
    load_stage(1, 1);

    int acc[4][8][4];
#pragma unroll
    for (int mm = 0; mm < 4; mm++)
#pragma unroll
        for (int nn = 0; nn < 8; nn++)
#pragma unroll
            for (int q = 0; q < 4; q++) acc[mm][nn][q] = 0;

    int rA = wm + (lane & 15);
    int rB = wn + ((lane >> 4) << 3) + (lane & 7);
    int ckA_lo = (lane >> 4);
    int ckB_lo = ((lane >> 3) & 1);

#pragma unroll 1
    for (int kt = 0; kt < KT; kt++) {
        if (kt == KT - 1) asm volatile("cp.async.wait_group 0;" ::: "memory");
        else              asm volatile("cp.async.wait_group 1;" ::: "memory");
        __syncthreads();
        if (kt + 2 < KT) load_stage((kt + 2) % 3, kt + 2);

        if (kt == HIT) {
#pragma unroll
            for (int mm = 0; mm < 4; mm++)
#pragma unroll
                for (int nn = 0; nn < 8; nn++)
#pragma unroll
                    for (int q = 0; q < 4; q++) acc[mm][nn][q] <<= 8;
        }

        uint32_t baseA = sb + (uint32_t)(kt % 3) * 49152u;
        uint32_t baseB = baseA + 16384u;

#pragma unroll
        for (int kk = 0; kk < 4; kk++) {
            uint32_t aF[4][4], bF[8][2];
            int ckA = kk * 2 + ckA_lo;
            int ckB = kk * 2 + ckB_lo;
#pragma unroll
            for (int mm = 0; mm < 4; mm++) {
                int row = rA + mm * 16;
                ldmx4(aF[mm], baseA + row * 128 + ((ckA ^ (row & 7)) << 4));
            }
#pragma unroll
            for (int p = 0; p < 4; p++) {
                int row = rB + p * 16;
                uint32_t r[4];
                ldmx4(r, baseB + row * 128 + ((ckB ^ (row & 7)) << 4));
                bF[p * 2][0] = r[0]; bF[p * 2][1] = r[1];
                bF[p * 2 + 1][0] = r[2]; bF[p * 2 + 1][1] = r[3];
            }
#pragma unroll
            for (int mm = 0; mm < 4; mm++)
#pragma unroll
                for (int nn = 0; nn < 8; nn++) {
                    if (UNS) mma_u8(acc[mm][nn], aF[mm], bF[nn]);
                    else     mma_s8(acc[mm][nn], aF[mm], bF[nn]);
                }
        }
    }

    // Epilogue: convert+store, fused column sum/sumsq
    int rE = m0 + wm + (lane >> 2);
    int cE = n0 + wn + 2 * (lane & 3);
#pragma unroll
    for (int nn = 0; nn < 8; nn++) {
        float s0 = 0.f, s1 = 0.f, q0 = 0.f, q1 = 0.f;
#pragma unroll
        for (int mm = 0; mm < 4; mm++) {
            float a0 = (float)acc[mm][nn][0] * scale;
            float a1 = (float)acc[mm][nn][1] * scale;
            float a2 = (float)acc[mm][nn][2] * scale;
            float a3 = (float)acc[mm][nn][3] * scale;
            float* base = g_h + (size_t)(rE + mm * 16) * 1024 + cE + nn * 8;
            *reinterpret_cast<float2*>(base) = make_float2(a0, a1);
            *reinterpret_cast<float2*>(base + 8 * 1024) = make_float2(a2, a3);
            s0 += a0 + a2; s1 += a1 + a3;
            q0 += a0 * a0 + a2 * a2; q1 += a1 * a1 + a3 * a3;
        }
#pragma unroll
        for (int o = 4; o <= 16; o <<= 1) {
            s0 += __shfl_xor_sync(0xFFFFFFFFu, s0, o);
            s1 += __shfl_xor_sync(0xFFFFFFFFu, s1, o);
            q0 += __shfl_xor_sync(0xFFFFFFFFu, q0, o);
            q1 += __shfl_xor_sync(0xFFFFFFFFu, q1, o);
        }
        if (lane < 4) {
            int c = cE + nn * 8;
            atomicAdd(&g_sum[layer][c], s0);
            atomicAdd(&g_sum[layer][c + 1], s1);
            atomicAdd(&g_sumsq[layer][c], q0);
            atomicAdd(&g_sumsq[layer][c + 1], q1);
        }
    }
}

// ---------------------------------------------------------------------------
// bnq: per-thread BN params (L2-hot stats), BN+ReLU+quantize for 4 rows
// (MLP=4). q in [0,65535]; hi/lo packed via __byte_perm.
// ---------------------------------------------------------------------------
__global__ __launch_bounds__(256) void bnq_kernel(const float* __restrict__ g,
                                                  const float* __restrict__ b,
                                                  int layer) {
    int r0 = blockIdx.x * 4;
    int t = threadIdx.x;
    int c = t * 4;

    float4 su = *reinterpret_cast<const float4*>(&g_sum[layer][c]);
    float4 sq = *reinterpret_cast<const float4*>(&g_sumsq[layer][c]);
    float4 gg = *reinterpret_cast<const float4*>(g + c);
    float4 bb = *reinterpret_cast<const float4*>(b + c);
    const float invB = 1.0f / 16384.0f;
    float sc[4], sh[4];
    {
        float sus[4] = {su.x, su.y, su.z, su.w};
        float sqs[4] = {sq.x, sq.y, sq.z, sq.w};
        float gs[4] = {gg.x, gg.y, gg.z, gg.w};
        float bs[4] = {bb.x, bb.y, bb.z, bb.w};
#pragma unroll
        for (int j = 0; j < 4; j++) {
            float m = sus[j] * invB;
            float var = sqs[j] * invB - m * m;
            sc[j] = gs[j] * rsqrtf(var + 1e-5f);
            sh[j] = bs[j] - m * sc[j];
        }
    }

    float4 h[4];
#pragma unroll
    for (int i = 0; i < 4; i++)
        h[i] = *reinterpret_cast<const float4*>(g_h + (size_t)(r0 + i) * 1024 + c);
#pragma unroll
    for (int i = 0; i < 4; i++) {
        float hv4[4] = {h[i].x, h[i].y, h[i].z, h[i].w};
        uint32_t qv[4];
#pragma unroll
        for (int j = 0; j < 4; j++) {
            float v = fmaxf(fmaf(hv4[j], sc[j], sh[j]), 0.0f);
            qv[j] = (uint32_t)min(65535, __float2int_rn(v * 8192.0f));
        }
        uint32_t lo01 = __byte_perm(qv[0], qv[1], 0x0040);
        uint32_t lo23 = __byte_perm(qv[2], qv[3], 0x0040);
        uint32_t lo = __byte_perm(lo01, lo23, 0x5410);
        uint32_t hi01 = __byte_perm(qv[0], qv[1], 0x0051);
        uint32_t hi23 = __byte_perm(qv[2], qv[3], 0x0051);
        uint32_t hi = __byte_perm(hi01, hi23, 0x5410);
        size_t r = (size_t)(r0 + i);
        *reinterpret_cast<uint32_t*>(g_act + r * 2048 + c) = hi;
        *reinterpret_cast<uint32_t*>(g_act + r * 2048 + 1024 + c) = lo;
    }
}

// ---------------------------------------------------------------------------
// Head with fused layer-3 BN+ReLU (pure fp32 from g_h)
// ---------------------------------------------------------------------------
__global__ __launch_bounds__(512) void head_kernel(
    const float* __restrict__ w4, const float* __restrict__ g,
    const float* __restrict__ b, float* __restrict__ out) {
    __shared__ float ws[10][1024];
    __shared__ float s_sc[1024], s_sh[1024];
    int tid = threadIdx.x;
    for (int i = tid; i < 10 * 1024; i += 512)
        ws[i >> 10][i & 1023] = (w4[i] >= 0.0f) ? 1.0f : -1.0f;
    const float invB = 1.0f / 16384.0f;
    for (int c = tid; c < 1024; c += 512) {
        float m = g_sum[2][c] * invB;
        float var = g_sumsq[2][c] * invB - m * m;
        float sc = g[c] * rsqrtf(var + 1e-5f);
        s_sc[c] = sc;
        s_sh[c] = b[c] - m * sc;
    }
    __syncthreads();

    int warp = tid >> 5, lane = tid & 31;
    size_t row = (size_t)blockIdx.x * 16 + warp;
    const float* h = g_h + row * 1024;

    float acc[10];
#pragma unroll
    for (int j = 0; j < 10; j++) acc[j] = 0.0f;

    for (int k = lane; k < 1024; k += 32) {
        float v = fmaxf(h[k] * s_sc[k] + s_sh[k], 0.0f);
#pragma unroll
        for (int j = 0; j < 10; j++) acc[j] += v * ws[j][k];
    }
#pragma unroll
    for (int j = 0; j < 10; j++) {
#pragma unroll
        for (int o = 16; o > 0; o >>= 1)
            acc[j] += __shfl_xor_sync(0xFFFFFFFFu, acc[j], o);
    }
    if (lane == 0) {
#pragma unroll
        for (int j = 0; j < 10; j++)
            out[row * 10 + j] = 1.0f / (1.0f + __expf(-acc[j]));
    }
}

// ---------------------------------------------------------------------------
// Launch
// ---------------------------------------------------------------------------
extern "C" void kernel_launch(void* const* d_in, const int* in_sizes, int n_in,
                              void* d_out, int out_size) {
    (void)in_sizes; (void)n_in; (void)out_size;
    const float* x  = (const float*)d_in[0];
    const float* w1 = (const float*)d_in[1];
    const float* g1 = (const float*)d_in[2];
    const float* b1 = (const float*)d_in[3];
    const float* w2 = (const float*)d_in[4];
    const float* g2 = (const float*)d_in[5];
    const float* b2 = (const float*)d_in[6];
    const float* w3 = (const float*)d_in[7];
    const float* g3 = (const float*)d_in[8];
    const float* b3 = (const float*)d_in[9];
    const float* w4 = (const float*)d_in[10];
    float* out = (float*)d_out;

    cudaFuncSetAttribute(gemm_s8_kernel<1792, 14, 0>,
                         cudaFuncAttributeMaxDynamicSharedMemorySize, GEMM_SMEM);
    cudaFuncSetAttribute(gemm_s8_kernel<2048, 16, 1>,
                         cudaFuncAttributeMaxDynamicSharedMemorySize, GEMM_SMEM);

    // prep_x + all binarize + stat zeroing in ONE launch
    prep_all_kernel<<<dim3(4096, 4), 256>>>(x, w1, w2, w3);

    // layer 1: s8 x s8, stride 1792, 14 k-tiles
    gemm_s8_kernel<1792, 14, 0><<<dim3(4, 128), 256, GEMM_SMEM>>>(1.0f / 4096.0f, 0);
    bnq_kernel<<<4096, 256>>>(g1, b1, 0);

    // layer 2: u8 x s8, stride 2048, 16 k-tiles
    gemm_s8_kernel<2048, 16, 1><<<dim3(4, 128), 256, GEMM_SMEM>>>(1.0f / 8192.0f, 1);
    bnq_kernel<<<4096, 256>>>(g2, b2, 1);

    // layer 3
    gemm_s8_kernel<2048, 16, 1><<<dim3(4, 128), 256, GEMM_SMEM>>>(1.0f / 8192.0f, 2);

    // head: fused BN3 + ReLU + binarized dot + sigmoid
    head_kernel<<<1024, 512>>>(w4, g3, b3, out);
}

// round 16
// speedup vs baseline: 1.1800x; 1.1800x over previous
#include <cuda_runtime.h>
#include <cuda_bf16.h>
#include <cstdint>

// ---------------------------------------------------------------------------
// Binarized MLP. Weights exactly +-1; activations in 16-bit fixed point
// v = s*(256*hi + lo) -> GEMM exact in int32 via two K-phases (acc <<= 8).
// Layer 1: hi s8 / lo s8, mma s8*s8.  Layers 2/3 (v>=0): hi u8 / lo u8,
// mma u8*s8.
// R16: revert GEMM to the 360.0us R14 config (R15 1-CTA/SM regressed: the
// sibling CTA covers barrier stalls). bnq upgraded to 8-row ILP.
// ---------------------------------------------------------------------------

#define BATCH 16384
#define GEMM_SMEM (3 * 32768)

__device__ __align__(256) int8_t g_act[(size_t)BATCH * 2048];    // hi | lo
__device__ __align__(256) int8_t g_wcat[3][(size_t)1024 * 2048]; // sign w per layer
__device__ __align__(256) float  g_h[(size_t)BATCH * 1024];
__device__ float g_sum[3][1024];
__device__ float g_sumsq[3][1024];

// ---------------------------------------------------------------------------
// PTX helpers (baseline PTX; compute_100 target has no tcgen05)
// ---------------------------------------------------------------------------
__device__ __forceinline__ uint32_t smem_u32(const void* p) {
    uint32_t a;
    asm("{ .reg .u64 t; cvta.to.shared.u64 t, %1; cvt.u32.u64 %0, t; }"
        : "=r"(a) : "l"(p));
    return a;
}
__device__ __forceinline__ void cp16(uint32_t dst, const void* src) {
    asm volatile("cp.async.cg.shared.global [%0], [%1], 16;"
                 :: "r"(dst), "l"(src) : "memory");
}
__device__ __forceinline__ void cp_commit() {
    asm volatile("cp.async.commit_group;" ::: "memory");
}
__device__ __forceinline__ void ldmx4(uint32_t* r, uint32_t addr) {
    asm volatile("ldmatrix.sync.aligned.m8n8.x4.shared.b16 {%0,%1,%2,%3}, [%4];"
                 : "=r"(r[0]), "=r"(r[1]), "=r"(r[2]), "=r"(r[3]) : "r"(addr));
}
__device__ __forceinline__ void mma_s8(int* c, const uint32_t* a, const uint32_t* b) {
    asm volatile(
        "mma.sync.aligned.m16n8k32.row.col.s32.s8.s8.s32 "
        "{%0,%1,%2,%3}, {%4,%5,%6,%7}, {%8,%9}, {%0,%1,%2,%3};"
        : "+r"(c[0]), "+r"(c[1]), "+r"(c[2]), "+r"(c[3])
        : "r"(a[0]), "r"(a[1]), "r"(a[2]), "r"(a[3]), "r"(b[0]), "r"(b[1]));
}
__device__ __forceinline__ void mma_u8(int* c, const uint32_t* a, const uint32_t* b) {
    asm volatile(
        "mma.sync.aligned.m16n8k32.row.col.s32.u8.s8.s32 "
        "{%0,%1,%2,%3}, {%4,%5,%6,%7}, {%8,%9}, {%0,%1,%2,%3};"
        : "+r"(c[0]), "+r"(c[1]), "+r"(c[2]), "+r"(c[3])
        : "r"(a[0]), "r"(a[1]), "r"(a[2]), "r"(a[3]), "r"(b[0]), "r"(b[1]));
}

// ---------------------------------------------------------------------------
// Merged prep: y == 0 -> prep_x (4 rows per block, MLP=4);
//              y in 1..3 -> binarize layer y-1 (blocks x < 256 active).
// ---------------------------------------------------------------------------
__global__ __launch_bounds__(256) void prep_all_kernel(
    const float* __restrict__ x, const float* __restrict__ w1,
    const float* __restrict__ w2, const float* __restrict__ w3) {
    int t = threadIdx.x;

    if (blockIdx.y == 0) {
        int r0 = blockIdx.x * 4;
        if (t < 196) {
            float4 xv[4];
#pragma unroll
            for (int i = 0; i < 4; i++)
                xv[i] = reinterpret_cast<const float4*>(x + (size_t)(r0 + i) * 784)[t];
#pragma unroll
            for (int i = 0; i < 4; i++) {
                float f[4] = {xv[i].x, xv[i].y, xv[i].z, xv[i].w};
                uint8_t hv[4], lv[4];
#pragma unroll
                for (int j = 0; j < 4; j++) {
                    int hi = __float2int_rn(f[j] * 16.0f);
                    hi = max(-127, min(127, hi));
                    int lo = __float2int_rn(f[j] * 4096.0f - 256.0f * hi);
                    lo = max(-128, min(127, lo));
                    hv[j] = (uint8_t)(int8_t)hi;
                    lv[j] = (uint8_t)(int8_t)lo;
                }
                int8_t* dst = g_act + (size_t)(r0 + i) * 1792;
                *reinterpret_cast<uchar4*>(dst + t * 4) =
                    make_uchar4(hv[0], hv[1], hv[2], hv[3]);
                *reinterpret_cast<uchar4*>(dst + 896 + t * 4) =
                    make_uchar4(lv[0], lv[1], lv[2], lv[3]);
            }
        } else if (t < 224) {
            int off = 784 + (t - 196) * 4;
#pragma unroll
            for (int i = 0; i < 4; i++) {
                int8_t* dst = g_act + (size_t)(r0 + i) * 1792;
                *reinterpret_cast<uchar4*>(dst + off) = make_uchar4(0, 0, 0, 0);
                *reinterpret_cast<uchar4*>(dst + 896 + off) = make_uchar4(0, 0, 0, 0);
            }
        }
        return;
    }

    int layer = blockIdx.y - 1;
    if (blockIdx.x >= 256) return;
    const float* w = (layer == 0) ? w1 : ((layer == 1) ? w2 : w3);
    int K = (layer == 0) ? 784 : 1024;
    int half = (layer == 0) ? 896 : 1024;
    int stride = half * 2;

    if (blockIdx.x == 0) {
        for (int j = t; j < 1024; j += 256) {
            g_sum[layer][j] = 0.0f;
            g_sumsq[layer][j] = 0.0f;
        }
    }

    int per_row = half >> 4;
    int idx = blockIdx.x * 256 + t;
    int n = idx / per_row;
    if (n >= 1024) return;
    int k16 = (idx - n * per_row) << 4;

    uint32_t pk[4] = {0, 0, 0, 0};
    if (k16 < K) {
        const float4* wp = reinterpret_cast<const float4*>(w + (size_t)n * K + k16);
#pragma unroll
        for (int q = 0; q < 4; q++) {
            float4 wv = wp[q];
            uint32_t b0 = (wv.x >= 0.0f) ? 0x01u : 0xFFu;
            uint32_t b1 = (wv.y >= 0.0f) ? 0x01u : 0xFFu;
            uint32_t b2 = (wv.z >= 0.0f) ? 0x01u : 0xFFu;
            uint32_t b3 = (wv.w >= 0.0f) ? 0x01u : 0xFFu;
            pk[q] = b0 | (b1 << 8) | (b2 << 16) | (b3 << 24);
        }
    }
    int4 v = make_int4((int)pk[0], (int)pk[1], (int)pk[2], (int)pk[3]);
    int8_t* base = g_wcat[layer] + (size_t)n * stride + k16;
    *reinterpret_cast<int4*>(base) = v;
    *reinterpret_cast<int4*>(base + half) = v;
}

// ---------------------------------------------------------------------------
// int8 GEMM: g_h = scale*(256*(hi@W) + lo@W), fused column stats.
// CTA 128x128, 4 warps (warp 64x64), k-tile 128B, 3-stage cp.async.
// grid = (N=8, M=128), 2 CTAs/SM. FROZEN at the 360.0us best configuration.
// ---------------------------------------------------------------------------
template <int LDA, int KT, int UNS>
__global__ __launch_bounds__(128, 2) void gemm_s8_kernel(float scale, int layer) {
    constexpr int HIT = KT / 2;
    extern __shared__ char smem[];
    uint32_t sb = smem_u32(smem);
    int tid = threadIdx.x, lane = tid & 31, warp = tid >> 5;
    int wm = (warp & 1) * 64;
    int wn = (warp >> 1) * 64;
    int n0 = blockIdx.x * 128, m0 = blockIdx.y * 128;
    const int8_t* A = g_act;
    const int8_t* W = g_wcat[layer];

    auto load_stage = [&](int s, int kt) {
        uint32_t baseA = sb + (uint32_t)s * 32768u;
        uint32_t baseB = baseA + 16384u;
        const int8_t* Ap = A + (size_t)m0 * LDA + kt * 128;
        const int8_t* Wp = W + (size_t)n0 * LDA + kt * 128;
#pragma unroll
        for (int i = 0; i < 8; i++) {
            int idx = tid + i * 128;
            int row = idx >> 3, ck = idx & 7;
            uint32_t sw = (uint32_t)(row * 128 + ((ck ^ (row & 7)) << 4));
            cp16(baseA + sw, Ap + (size_t)row * LDA + ck * 16);
            cp16(baseB + sw, Wp + (size_t)row * LDA + ck * 16);
        }
        cp_commit();
    };

    load_stage(0, 0);
    load_stage(1, 1);

    int acc[4][8][4];
#pragma unroll
    for (int mm = 0; mm < 4; mm++)
#pragma unroll
        for (int nn = 0; nn < 8; nn++)
#pragma unroll
            for (int q = 0; q < 4; q++) acc[mm][nn][q] = 0;

    int rA = wm + (lane & 15);
    int rB = wn + ((lane >> 4) << 3) + (lane & 7);
    int ckA_lo = (lane >> 4);
    int ckB_lo = ((lane >> 3) & 1);

#pragma unroll 1
    for (int kt = 0; kt < KT; kt++) {
        if (kt == KT - 1) asm volatile("cp.async.wait_group 0;" ::: "memory");
        else              asm volatile("cp.async.wait_group 1;" ::: "memory");
        __syncthreads();
        if (kt + 2 < KT) load_stage((kt + 2) % 3, kt + 2);

        if (kt == HIT) {
#pragma unroll
            for (int mm = 0; mm < 4; mm++)
#pragma unroll
                for (int nn = 0; nn < 8; nn++)
#pragma unroll
                    for (int q = 0; q < 4; q++) acc[mm][nn][q] <<= 8;
        }

        uint32_t baseA = sb + (uint32_t)(kt % 3) * 32768u;
        uint32_t baseB = baseA + 16384u;

#pragma unroll
        for (int kk = 0; kk < 4; kk++) {
            uint32_t aF[4][4], bF[8][2];
            int ckA = kk * 2 + ckA_lo;
            int ckB = kk * 2 + ckB_lo;
#pragma unroll
            for (int mm = 0; mm < 4; mm++) {
                int row = rA + mm * 16;
                ldmx4(aF[mm], baseA + row * 128 + ((ckA ^ (row & 7)) << 4));
            }
#pragma unroll
            for (int p = 0; p < 4; p++) {
                int row = rB + p * 16;
                uint32_t r[4];
                ldmx4(r, baseB + row * 128 + ((ckB ^ (row & 7)) << 4));
                bF[p * 2][0] = r[0]; bF[p * 2][1] = r[1];
                bF[p * 2 + 1][0] = r[2]; bF[p * 2 + 1][1] = r[3];
            }
#pragma unroll
            for (int mm = 0; mm < 4; mm++)
#pragma unroll
                for (int nn = 0; nn < 8; nn++) {
                    if (UNS) mma_u8(acc[mm][nn], aF[mm], bF[nn]);
                    else     mma_s8(acc[mm][nn], aF[mm], bF[nn]);
                }
        }
    }

    // Epilogue: convert+store, fused column sum/sumsq
    int rE = m0 + wm + (lane >> 2);
    int cE = n0 + wn + 2 * (lane & 3);
#pragma unroll
    for (int nn = 0; nn < 8; nn++) {
        float s0 = 0.f, s1 = 0.f, q0 = 0.f, q1 = 0.f;
#pragma unroll
        for (int mm = 0; mm < 4; mm++) {
            float a0 = (float)acc[mm][nn][0] * scale;
            float a1 = (float)acc[mm][nn][1] * scale;
            float a2 = (float)acc[mm][nn][2] * scale;
            float a3 = (float)acc[mm][nn][3] * scale;
            float* base = g_h + (size_t)(rE + mm * 16) * 1024 + cE + nn * 8;
            *reinterpret_cast<float2*>(base) = make_float2(a0, a1);
            *reinterpret_cast<float2*>(base + 8 * 1024) = make_float2(a2, a3);
            s0 += a0 + a2; s1 += a1 + a3;
            q0 += a0 * a0 + a2 * a2; q1 += a1 * a1 + a3 * a3;
        }
#pragma unroll
        for (int o = 4; o <= 16; o <<= 1) {
            s0 += __shfl_xor_sync(0xFFFFFFFFu, s0, o);
            s1 += __shfl_xor_sync(0xFFFFFFFFu, s1, o);
            q0 += __shfl_xor_sync(0xFFFFFFFFu, q0, o);
            q1 += __shfl_xor_sync(0xFFFFFFFFu, q1, o);
        }
        if (lane < 4) {
            int c = cE + nn * 8;
            atomicAdd(&g_sum[layer][c], s0);
            atomicAdd(&g_sum[layer][c + 1], s1);
            atomicAdd(&g_sumsq[layer][c], q0);
            atomicAdd(&g_sumsq[layer][c + 1], q1);
        }
    }
}

// ---------------------------------------------------------------------------
// bnq: per-thread BN params (L2-hot stats), BN+ReLU+quantize for 8 rows
// (MLP=8). q in [0,65535]; hi/lo packed via __byte_perm.
// ---------------------------------------------------------------------------
__global__ __launch_bounds__(256) void bnq_kernel(const float* __restrict__ g,
                                                  const float* __restrict__ b,
                                                  int layer) {
    int r0 = blockIdx.x * 8;             // grid 2048
    int t = threadIdx.x;
    int c = t * 4;

    float4 su = *reinterpret_cast<const float4*>(&g_sum[layer][c]);
    float4 sq = *reinterpret_cast<const float4*>(&g_sumsq[layer][c]);
    float4 gg = *reinterpret_cast<const float4*>(g + c);
    float4 bb = *reinterpret_cast<const float4*>(b + c);
    const float invB = 1.0f / 16384.0f;
    float sc[4], sh[4];
    {
        float sus[4] = {su.x, su.y, su.z, su.w};
        float sqs[4] = {sq.x, sq.y, sq.z, sq.w};
        float gs[4] = {gg.x, gg.y, gg.z, gg.w};
        float bs[4] = {bb.x, bb.y, bb.z, bb.w};
#pragma unroll
        for (int j = 0; j < 4; j++) {
            float m = sus[j] * invB;
            float var = sqs[j] * invB - m * m;
            sc[j] = gs[j] * rsqrtf(var + 1e-5f);
            sh[j] = bs[j] - m * sc[j];
        }
    }

    float4 h[8];
#pragma unroll
    for (int i = 0; i < 8; i++)
        h[i] = *reinterpret_cast<const float4*>(g_h + (size_t)(r0 + i) * 1024 + c);
#pragma unroll
    for (int i = 0; i < 8; i++) {
        float hv4[4] = {h[i].x, h[i].y, h[i].z, h[i].w};
        uint32_t qv[4];
#pragma unroll
        for (int j = 0; j < 4; j++) {
            float v = fmaxf(fmaf(hv4[j], sc[j], sh[j]), 0.0f);
            qv[j] = (uint32_t)min(65535, __float2int_rn(v * 8192.0f));
        }
        uint32_t lo01 = __byte_perm(qv[0], qv[1], 0x0040);
        uint32_t lo23 = __byte_perm(qv[2], qv[3], 0x0040);
        uint32_t lo = __byte_perm(lo01, lo23, 0x5410);
        uint32_t hi01 = __byte_perm(qv[0], qv[1], 0x0051);
        uint32_t hi23 = __byte_perm(qv[2], qv[3], 0x0051);
        uint32_t hi = __byte_perm(hi01, hi23, 0x5410);
        size_t r = (size_t)(r0 + i);
        *reinterpret_cast<uint32_t*>(g_act + r * 2048 + c) = hi;
        *reinterpret_cast<uint32_t*>(g_act + r * 2048 + 1024 + c) = lo;
    }
}

// ---------------------------------------------------------------------------
// Head with fused layer-3 BN+ReLU (pure fp32 from g_h)
// ---------------------------------------------------------------------------
__global__ __launch_bounds__(512) void head_kernel(
    const float* __restrict__ w4, const float* __restrict__ g,
    const float* __restrict__ b, float* __restrict__ out) {
    __shared__ float ws[10][1024];
    __shared__ float s_sc[1024], s_sh[1024];
    int tid = threadIdx.x;
    for (int i = tid; i < 10 * 1024; i += 512)
        ws[i >> 10][i & 1023] = (w4[i] >= 0.0f) ? 1.0f : -1.0f;
    const float invB = 1.0f / 16384.0f;
    for (int c = tid; c < 1024; c += 512) {
        float m = g_sum[2][c] * invB;
        float var = g_sumsq[2][c] * invB - m * m;
        float sc = g[c] * rsqrtf(var + 1e-5f);
        s_sc[c] = sc;
        s_sh[c] = b[c] - m * sc;
    }
    __syncthreads();

    int warp = tid >> 5, lane = tid & 31;
    size_t row = (size_t)blockIdx.x * 16 + warp;
    const float* h = g_h + row * 1024;

    float acc[10];
#pragma unroll
    for (int j = 0; j < 10; j++) acc[j] = 0.0f;

    for (int k = lane; k < 1024; k += 32) {
        float v = fmaxf(h[k] * s_sc[k] + s_sh[k], 0.0f);
#pragma unroll
        for (int j = 0; j < 10; j++) acc[j] += v * ws[j][k];
    }
#pragma unroll
    for (int j = 0; j < 10; j++) {
#pragma unroll
        for (int o = 16; o > 0; o >>= 1)
            acc[j] += __shfl_xor_sync(0xFFFFFFFFu, acc[j], o);
    }
    if (lane == 0) {
#pragma unroll
        for (int j = 0; j < 10; j++)
            out[row * 10 + j] = 1.0f / (1.0f + __expf(-acc[j]));
    }
}

// ---------------------------------------------------------------------------
// Launch
// ---------------------------------------------------------------------------
extern "C" void kernel_launch(void* const* d_in, const int* in_sizes, int n_in,
                              void* d_out, int out_size) {
    (void)in_sizes; (void)n_in; (void)out_size;
    const float* x  = (const float*)d_in[0];
    const float* w1 = (const float*)d_in[1];
    const float* g1 = (const float*)d_in[2];
    const float* b1 = (const float*)d_in[3];
    const float* w2 = (const float*)d_in[4];
    const float* g2 = (const float*)d_in[5];
    const float* b2 = (const float*)d_in[6];
    const float* w3 = (const float*)d_in[7];
    const float* g3 = (const float*)d_in[8];
    const float* b3 = (const float*)d_in[9];
    const float* w4 = (const float*)d_in[10];
    float* out = (float*)d_out;

    cudaFuncSetAttribute(gemm_s8_kernel<1792, 14, 0>,
                         cudaFuncAttributeMaxDynamicSharedMemorySize, GEMM_SMEM);
    cudaFuncSetAttribute(gemm_s8_kernel<2048, 16, 1>,
                         cudaFuncAttributeMaxDynamicSharedMemorySize, GEMM_SMEM);

    // prep_x + all binarize + stat zeroing in ONE launch
    prep_all_kernel<<<dim3(4096, 4), 256>>>(x, w1, w2, w3);

    // layer 1: s8 x s8, stride 1792, 14 k-tiles
    gemm_s8_kernel<1792, 14, 0><<<dim3(8, 128), 128, GEMM_SMEM>>>(1.0f / 4096.0f, 0);
    bnq_kernel<<<2048, 256>>>(g1, b1, 0);

    // layer 2: u8 x s8, stride 2048, 16 k-tiles
    gemm_s8_kernel<2048, 16, 1><<<dim3(8, 128), 128, GEMM_SMEM>>>(1.0f / 8192.0f, 1);
    bnq_kernel<<<2048, 256>>>(g2, b2, 1);

    // layer 3
    gemm_s8_kernel<2048, 16, 1><<<dim3(8, 128), 128, GEMM_SMEM>>>(1.0f / 8192.0f, 2);

    // head: fused BN3 + ReLU + binarized dot + sigmoid
    head_kernel<<<1024, 512>>>(w4, g3, b3, out);
}